// round 15
// baseline (speedup 1.0000x reference)
#include <cuda_runtime.h>
#include <cuda_bf16.h>

// Problem constants
#define QL  2048
#define KLN 2048
#define DM  1024
#define NH  16
#define BB  4
#define QT  32
#define KT  32
#define NTRI 528                 // lower-triangle 64x64 tiles per (b,h)
#define EL_A (BB * QL * DM)      // 8388608
#define GRP_A (EL_A / 8)         // 1048576 = 1<<20
#define EL_W (DM * DM)           // 1048576
#define GRP_W (EL_W / 8)         // 131072 = 1<<17

// Static device scratch (no cudaMalloc allowed)
__device__ float g_Qp[(size_t)EL_A];
__device__ float g_Kp[(size_t)EL_A];
__device__ float g_Vp[(size_t)EL_A];
__device__ float g_m[BB * NH * QL];
__device__ float g_l[BB * NH * QL];
__device__ float g_P[(size_t)BB * NH * NTRI * 4096];   // per-tile exp(s - m_kt)
__device__ float g_mkt[(size_t)BB * NH * KT * QL];     // running max after tile kt
// split-bf16 operand buffers
__device__ __nv_bfloat16 g_Ah[(size_t)3 * EL_A];       // q,k,v hi
__device__ __nv_bfloat16 g_Al[(size_t)3 * EL_A];       // q,k,v lo
__device__ __nv_bfloat16 g_Oh[(size_t)EL_A];           // attn-O hi (from pass1)
__device__ __nv_bfloat16 g_Ol[(size_t)EL_A];           // attn-O lo
__device__ __nv_bfloat16 g_Wh[(size_t)4 * EL_W];       // Wq,Wk,Wv,Wo hi
__device__ __nv_bfloat16 g_Wl[(size_t)4 * EL_W];       // lo

// ---------------------------------------------------------------------------
// Helpers (base-ISA only — toolchain lowers via compute_103, no 'a' features)
// ---------------------------------------------------------------------------
__device__ __forceinline__ unsigned smem_u32(const void* p) {
    unsigned a;
    asm("{ .reg .u64 t; cvta.to.shared.u64 t, %1; cvt.u32.u64 %0, t; }" : "=r"(a) : "l"(p));
    return a;
}
__device__ __forceinline__ float2 ffma2(float2 a, float2 b, float2 c) {
    union U { float2 f; unsigned long long u; } A, B, C;
    A.f = a; B.f = b; C.f = c;
    asm("fma.rn.f32x2 %0, %1, %2, %0;" : "+l"(C.u) : "l"(A.u), "l"(B.u));
    return C.f;
}
__device__ __forceinline__ void ldsm4(unsigned& r0, unsigned& r1, unsigned& r2,
                                      unsigned& r3, unsigned addr) {
    asm volatile("ldmatrix.sync.aligned.m8n8.x4.shared.b16 {%0,%1,%2,%3}, [%4];"
                 : "=r"(r0), "=r"(r1), "=r"(r2), "=r"(r3) : "r"(addr));
}
__device__ __forceinline__ void mma16816(float* c, const unsigned* a,
                                         unsigned b0, unsigned b1) {
    asm volatile(
        "mma.sync.aligned.m16n8k16.row.col.f32.bf16.bf16.f32 "
        "{%0,%1,%2,%3}, {%4,%5,%6,%7}, {%8,%9}, {%0,%1,%2,%3};"
        : "+f"(c[0]), "+f"(c[1]), "+f"(c[2]), "+f"(c[3])
        : "r"(a[0]), "r"(a[1]), "r"(a[2]), "r"(a[3]), "r"(b0), "r"(b1));
}
__device__ __forceinline__ void cp16(unsigned dst, const void* src) {
    asm volatile("cp.async.cg.shared.global [%0], [%1], 16;"
                 :: "r"(dst), "l"(src) : "memory");
}
#define CP_COMMIT() asm volatile("cp.async.commit_group;" ::: "memory")
#define CP_WAIT1()  asm volatile("cp.async.wait_group 1;" ::: "memory")

// ---------------------------------------------------------------------------
// split_all: one kernel splits q,k,v (3 x 8M elems) and 4 W (1M elems each)
// into bf16 hi/lo. grid = 14336 x 256.
// ---------------------------------------------------------------------------
__global__ void __launch_bounds__(256) split_all(
    const float* __restrict__ q, const float* __restrict__ k, const float* __restrict__ v,
    const float* __restrict__ Wq, const float* __restrict__ Wk,
    const float* __restrict__ Wv, const float* __restrict__ Wo) {
    const int i = blockIdx.x * 256 + threadIdx.x;
    const float* src;
    __nv_bfloat16 *hi, *lo;
    size_t off;
    if (i < 3 * GRP_A) {
        const int a = i >> 20;
        off = (size_t)(i & (GRP_A - 1)) * 8;
        src = (a == 0) ? q : (a == 1) ? k : v;
        hi = g_Ah + (size_t)a * EL_A;
        lo = g_Al + (size_t)a * EL_A;
    } else {
        const int j = i - 3 * GRP_A;
        if (j >= 4 * GRP_W) return;
        const int w = j >> 17;
        off = (size_t)(j & (GRP_W - 1)) * 8;
        src = (w == 0) ? Wq : (w == 1) ? Wk : (w == 2) ? Wv : Wo;
        hi = g_Wh + (size_t)w * EL_W;
        lo = g_Wl + (size_t)w * EL_W;
    }
    const float4 a4 = *(const float4*)(src + off);
    const float4 b4 = *(const float4*)(src + off + 4);
    float v8[8] = {a4.x, a4.y, a4.z, a4.w, b4.x, b4.y, b4.z, b4.w};
    __align__(16) __nv_bfloat16 h[8], l[8];
#pragma unroll
    for (int u = 0; u < 8; u++) {
        h[u] = __float2bfloat16(v8[u]);
        l[u] = __float2bfloat16(v8[u] - __bfloat162float(h[u]));
    }
    *(uint4*)(hi + off) = *(const uint4*)h;
    *(uint4*)(lo + off) = *(const uint4*)l;
}

// ---------------------------------------------------------------------------
// Split-bf16 GEMM body (mma.sync + cp.async 3-stage). CTA 128x128, BK=32,
// 16 warps (warp tile 32x32), 512 threads, 96KB dynamic smem.
// C[m0..+128, n0..+128] = A @ W^T, 3 terms Ah*Bh + Ah*Bl + Al*Bh.
// ---------------------------------------------------------------------------
#define T_AH 0
#define T_AL 8192
#define T_BH 16384
#define T_BL 24576
#define STG  32768
#define NSTG 3

__device__ __forceinline__ void gemm_body(
    const __nv_bfloat16* __restrict__ Ahi, const __nv_bfloat16* __restrict__ Alo,
    const __nv_bfloat16* __restrict__ Bhi, const __nv_bfloat16* __restrict__ Blo,
    float* __restrict__ C, int m0, int n0, char* sm, unsigned smb) {
    const int tid = threadIdx.x, lane = tid & 31, wid = tid >> 5;
    const int wm = wid & 3, wn = wid >> 2;           // warp tile: 32 m x 32 n

    const int lrow = tid >> 2;                        // 0..127
    const int lu0  = tid & 3;                         // unit 0..3
    const __nv_bfloat16* gsrc[4] = {
        Ahi + (size_t)(m0 + lrow) * 1024 + lu0 * 8,
        Alo + (size_t)(m0 + lrow) * 1024 + lu0 * 8,
        Bhi + (size_t)(n0 + lrow) * 1024 + lu0 * 8,
        Blo + (size_t)(n0 + lrow) * 1024 + lu0 * 8};
    const int swr = (lrow >> 1) & 3;
    const unsigned st0 = (unsigned)(lrow * 64 + (lu0 ^ swr) * 16);

    const int rA   = wm * 32 + (lane & 7) + 8 * ((lane >> 3) & 1);
    const int selA = (lane >> 4) & 1;
    const int rB   = wn * 32 + (lane & 7) + 8 * ((lane >> 4) & 1);
    const int selB = (lane >> 3) & 1;
    unsigned offA[2]; int swA[2];
#pragma unroll
    for (int mt = 0; mt < 2; mt++) {
        const int row = rA + mt * 16;
        offA[mt] = row * 64;  swA[mt] = (row >> 1) & 3;
    }
    unsigned offB[2]; int swB[2];
#pragma unroll
    for (int p = 0; p < 2; p++) {
        const int row = rB + p * 16;
        offB[p] = row * 64;  swB[p] = (row >> 1) & 3;
    }

    float acc[2][4][4];
#pragma unroll
    for (int mt = 0; mt < 2; mt++)
#pragma unroll
        for (int nt = 0; nt < 4; nt++)
#pragma unroll
            for (int r = 0; r < 4; r++) acc[mt][nt][r] = 0.f;

#define G_ISSUE(slot, c) do { \
    const unsigned base_ = smb + (slot) * STG; \
    _Pragma("unroll") \
    for (int t = 0; t < 4; t++) \
        cp16(base_ + t * 8192 + st0, gsrc[t] + (c) * 32); \
    } while (0)

    G_ISSUE(0, 0); CP_COMMIT();
    G_ISSUE(1, 1); CP_COMMIT();

    for (int c = 0; c < 32; c++) {
        CP_WAIT1();
        __syncthreads();
        if (c + 2 < 32) G_ISSUE((c + 2) % NSTG, c + 2);
        CP_COMMIT();
        const unsigned sb = smb + (c % NSTG) * STG;
#pragma unroll
        for (int ks = 0; ks < 2; ks++) {
            unsigned ah[2][4], al[2][4];
#pragma unroll
            for (int mt = 0; mt < 2; mt++) {
                const unsigned ua = (unsigned)(((ks * 2 + selA) ^ swA[mt]) * 16);
                ldsm4(ah[mt][0], ah[mt][1], ah[mt][2], ah[mt][3], sb + T_AH + offA[mt] + ua);
                ldsm4(al[mt][0], al[mt][1], al[mt][2], al[mt][3], sb + T_AL + offA[mt] + ua);
            }
            unsigned bh[2][4], bl[2][4];
#pragma unroll
            for (int p = 0; p < 2; p++) {
                const unsigned ub = (unsigned)(((ks * 2 + selB) ^ swB[p]) * 16);
                ldsm4(bh[p][0], bh[p][1], bh[p][2], bh[p][3], sb + T_BH + offB[p] + ub);
                ldsm4(bl[p][0], bl[p][1], bl[p][2], bl[p][3], sb + T_BL + offB[p] + ub);
            }
#pragma unroll
            for (int mt = 0; mt < 2; mt++)
#pragma unroll
                for (int nt = 0; nt < 4; nt++) {
                    const int p = nt >> 1, q = (nt & 1) * 2;
                    mma16816(acc[mt][nt], ah[mt], bh[p][q], bh[p][q + 1]);
                    mma16816(acc[mt][nt], ah[mt], bl[p][q], bl[p][q + 1]);
                    mma16816(acc[mt][nt], al[mt], bh[p][q], bh[p][q + 1]);
                }
        }
    }
#undef G_ISSUE

#pragma unroll
    for (int mt = 0; mt < 2; mt++)
#pragma unroll
        for (int nt = 0; nt < 4; nt++) {
            const int row = m0 + wm * 32 + mt * 16 + (lane >> 2);
            const int col = n0 + wn * 32 + nt * 8 + (lane & 3) * 2;
            *(float2*)(C + (size_t)row * 1024 + col) =
                make_float2(acc[mt][nt][0], acc[mt][nt][1]);
            *(float2*)(C + (size_t)(row + 8) * 1024 + col) =
                make_float2(acc[mt][nt][2], acc[mt][nt][3]);
        }
}

// ---------------------------------------------------------------------------
// gemm3: all three projections in one launch. grid = (8, 64, 3), 512 thr.
// ---------------------------------------------------------------------------
__global__ void __launch_bounds__(512) gemm3(
    float* __restrict__ pQ, float* __restrict__ pK, float* __restrict__ pV) {
    extern __shared__ char sm[];
    const unsigned smb = smem_u32(sm);
    const int z = blockIdx.z;
    float* C = (z == 0) ? pQ : (z == 1) ? pK : pV;
    gemm_body(g_Ah + (size_t)z * EL_A, g_Al + (size_t)z * EL_A,
              g_Wh + (size_t)z * EL_W, g_Wl + (size_t)z * EL_W,
              C, blockIdx.y * 128, blockIdx.x * 128, sm, smb);
}

// ---------------------------------------------------------------------------
// Pass 1: causal flash attention. float4 LDS micro-kernel (3x fewer LDS).
// Streams p = exp(s - m_kt) to g_P, m_kt to g_mkt; epilogue writes the bf16
// hi/lo split of normalized O directly (feeds the Wo GEMM).
// ---------------------------------------------------------------------------
__global__ void __launch_bounds__(256) attn_pass1() {
    __shared__ float Qs[64 * 64];
    __shared__ float KV[64 * 64];
    __shared__ float Ps[64 * 64];
    const int tid = threadIdx.x;
    const int tx = tid & 15, ty = tid >> 4;
    const int qt = blockIdx.x;
    const int bh = blockIdx.y;
    const int b = bh >> 4, h = bh & 15;
    const int q0 = qt * 64;

    {
        const int f = tid & 15, r0 = tid >> 4;
#pragma unroll
        for (int rr = 0; rr < 4; rr++) {
            const int r = r0 + rr * 16;
            *(float4*)&Qs[r * 64 + f * 4] =
                *(const float4*)(g_Qp + (size_t)(b * QL + q0 + r) * DM + h * 64 + f * 4);
        }
    }
    float2 Oacc[4][2];
#pragma unroll
    for (int i = 0; i < 4; i++) { Oacc[i][0] = make_float2(0.f, 0.f); Oacc[i][1] = make_float2(0.f, 0.f); }
    float mrow[4], lrow[4];
#pragma unroll
    for (int i = 0; i < 4; i++) { mrow[i] = -1e30f; lrow[i] = 0.f; }

    for (int kt = 0; kt <= qt; kt++) {
        const int k0 = kt * 64;
        const bool diag = (kt == qt);
        __syncthreads();
        {   // load K tile transposed: KV[d][c]
            const int c = tid & 63, dq = tid >> 6;
            const float* kg = g_Kp + (size_t)(b * KLN + k0 + c) * DM + h * 64 + dq * 16;
            float4 vv[4];
            vv[0] = *(const float4*)(kg + 0);  vv[1] = *(const float4*)(kg + 4);
            vv[2] = *(const float4*)(kg + 8);  vv[3] = *(const float4*)(kg + 12);
            const float* vp = (const float*)vv;
#pragma unroll
            for (int u = 0; u < 16; u++) KV[(dq * 16 + u) * 64 + c] = vp[u];
        }
        __syncthreads();
        // S = Q @ K^T : 4-step d, float4 LDS
        float2 S[4][2];
#pragma unroll
        for (int i = 0; i < 4; i++) { S[i][0] = make_float2(0.f, 0.f); S[i][1] = make_float2(0.f, 0.f); }
#pragma unroll 4
        for (int d4 = 0; d4 < 64; d4 += 4) {
            float4 bv[4], av[4];
#pragma unroll
            for (int u = 0; u < 4; u++) bv[u] = *(const float4*)&KV[(d4 + u) * 64 + tx * 4];
#pragma unroll
            for (int i = 0; i < 4; i++) av[i] = *(const float4*)&Qs[(ty * 4 + i) * 64 + d4];
#pragma unroll
            for (int u = 0; u < 4; u++) {
                const float2 b0 = make_float2(bv[u].x, bv[u].y);
                const float2 b1 = make_float2(bv[u].z, bv[u].w);
#pragma unroll
                for (int i = 0; i < 4; i++) {
                    const float a = (u == 0) ? av[i].x : (u == 1) ? av[i].y
                                  : (u == 2) ? av[i].z : av[i].w;
                    const float2 ap = make_float2(a, a);
                    S[i][0] = ffma2(ap, b0, S[i][0]);
                    S[i][1] = ffma2(ap, b1, S[i][1]);
                }
            }
        }
        __syncthreads();                              // K reads done; reuse KV for V
        {   // load V tile natural: KV[c][d]
            const int f = tid & 15, c0 = tid >> 4;
#pragma unroll
            for (int rr = 0; rr < 4; rr++) {
                const int c = c0 + rr * 16;
                *(float4*)&KV[c * 64 + f * 4] =
                    *(const float4*)(g_Vp + (size_t)(b * KLN + k0 + c) * DM + h * 64 + f * 4);
            }
        }
        float sv[4][4];
#pragma unroll
        for (int i = 0; i < 4; i++) {
            sv[i][0] = S[i][0].x * 0.125f;  sv[i][1] = S[i][0].y * 0.125f;
            sv[i][2] = S[i][1].x * 0.125f;  sv[i][3] = S[i][1].y * 0.125f;
        }
        if (diag) {
#pragma unroll
            for (int i = 0; i < 4; i++)
#pragma unroll
                for (int j = 0; j < 4; j++)
                    if (tx * 4 + j > ty * 4 + i) sv[i][j] = -1e30f;
        }
        float* ptile = g_P + ((size_t)bh * NTRI + (size_t)qt * (qt + 1) / 2 + kt) * 4096;
#pragma unroll
        for (int i = 0; i < 4; i++) {
            float tm = fmaxf(fmaxf(sv[i][0], sv[i][1]), fmaxf(sv[i][2], sv[i][3]));
#pragma unroll
            for (int m = 8; m >= 1; m >>= 1) tm = fmaxf(tm, __shfl_xor_sync(0xffffffffu, tm, m));
            const float mn = fmaxf(mrow[i], tm);
            const float alpha = __expf(mrow[i] - mn);
            mrow[i] = mn;
            float p[4];
#pragma unroll
            for (int j = 0; j < 4; j++)
                p[j] = (sv[i][j] <= -1e29f) ? 0.f : __expf(sv[i][j] - mn);
            float rs = p[0] + p[1] + p[2] + p[3];
#pragma unroll
            for (int m = 8; m >= 1; m >>= 1) rs += __shfl_xor_sync(0xffffffffu, rs, m);
            lrow[i] = lrow[i] * alpha + rs;
            Oacc[i][0].x *= alpha; Oacc[i][0].y *= alpha;
            Oacc[i][1].x *= alpha; Oacc[i][1].y *= alpha;
            *(float2*)&Ps[(ty * 4 + i) * 64 + tx * 4]     = make_float2(p[0], p[1]);
            *(float2*)&Ps[(ty * 4 + i) * 64 + tx * 4 + 2] = make_float2(p[2], p[3]);
            *(float4*)(ptile + (ty * 4 + i) * 64 + tx * 4) =
                make_float4(p[0], p[1], p[2], p[3]);
        }
        if (tx == 0) {
            float* mk = g_mkt + ((size_t)bh * KT + kt) * QL + q0;
#pragma unroll
            for (int i = 0; i < 4; i++) mk[ty * 4 + i] = mrow[i];
        }
        __syncthreads();                              // V + P staged
        // O += P @ V : 4-step c, float4 LDS
#pragma unroll 4
        for (int c4 = 0; c4 < 64; c4 += 4) {
            float4 bv[4], av[4];
#pragma unroll
            for (int u = 0; u < 4; u++) bv[u] = *(const float4*)&KV[(c4 + u) * 64 + tx * 4];
#pragma unroll
            for (int i = 0; i < 4; i++) av[i] = *(const float4*)&Ps[(ty * 4 + i) * 64 + c4];
#pragma unroll
            for (int u = 0; u < 4; u++) {
                const float2 b0 = make_float2(bv[u].x, bv[u].y);
                const float2 b1 = make_float2(bv[u].z, bv[u].w);
#pragma unroll
                for (int i = 0; i < 4; i++) {
                    const float a = (u == 0) ? av[i].x : (u == 1) ? av[i].y
                                  : (u == 2) ? av[i].z : av[i].w;
                    const float2 ap = make_float2(a, a);
                    Oacc[i][0] = ffma2(ap, b0, Oacc[i][0]);
                    Oacc[i][1] = ffma2(ap, b1, Oacc[i][1]);
                }
            }
        }
    }
    // epilogue: normalize, write O directly as bf16 hi/lo split + save (m, l)
#pragma unroll
    for (int i = 0; i < 4; i++) {
        const float inv = (lrow[i] > 0.f) ? (1.f / lrow[i]) : 0.f;
        const float o[4] = {Oacc[i][0].x * inv, Oacc[i][0].y * inv,
                            Oacc[i][1].x * inv, Oacc[i][1].y * inv};
        __align__(8) __nv_bfloat16 h4[4], l4[4];
#pragma unroll
        for (int u = 0; u < 4; u++) {
            h4[u] = __float2bfloat16(o[u]);
            l4[u] = __float2bfloat16(o[u] - __bfloat162float(h4[u]));
        }
        const size_t idx = (size_t)(b * QL + q0 + ty * 4 + i) * DM + h * 64 + tx * 4;
        *(uint2*)(g_Oh + idx) = *(const uint2*)h4;
        *(uint2*)(g_Ol + idx) = *(const uint2*)l4;
    }
    if (tx == 0) {
#pragma unroll
        for (int i = 0; i < 4; i++) {
            const int idx = bh * QL + q0 + ty * 4 + i;
            g_m[idx] = mrow[i];
            g_l[idx] = lrow[i];
        }
    }
}

// ---------------------------------------------------------------------------
// Fused final launch: blocks [0,512) do the Wo GEMM (tensor-bound);
// blocks [512, 512+16384) do pass2 rescale+store (DRAM-bound) — they co-run.
// 512 threads; pass2 blocks process 4 tiles each (2 concurrently x 2 iters).
// ---------------------------------------------------------------------------
__global__ void __launch_bounds__(512) gemm_wo_pass2(
    float* __restrict__ out, float* __restrict__ attn, int do_attn) {
    extern __shared__ char sm[];
    const int bid = blockIdx.x;
    if (bid < 512) {
        const unsigned smb = smem_u32(sm);
        gemm_body(g_Oh, g_Ol, g_Wh + (size_t)3 * EL_W, g_Wl + (size_t)3 * EL_W,
                  out, (bid >> 3) * 128, (bid & 7) * 128, sm, smb);
        return;
    }
    if (!do_attn) return;
    const int stid = threadIdx.x & 255;
    const int tx = stid & 15, ty = stid >> 4;
#pragma unroll
    for (int it = 0; it < 2; it++) {
        const int tl = (bid - 512) * 4 + it * 2 + (threadIdx.x >> 8);
        const int bh = tl >> 10;
        const int rem = tl & 1023;
        const int qt = rem >> 5, kt = rem & 31;
        const int q0 = qt * 64, k0 = kt * 64;
        float* out0 = attn + ((size_t)bh * QL + q0) * KLN + k0;
        if (kt > qt) {      // fully masked: zeros
            const int f = stid & 15, r0 = stid >> 4;
            const float4 z = make_float4(0.f, 0.f, 0.f, 0.f);
#pragma unroll
            for (int rr = 0; rr < 4; rr++)
                *(float4*)(out0 + (size_t)(r0 + rr * 16) * KLN + f * 4) = z;
            continue;
        }
        const float* ptile = g_P + ((size_t)bh * NTRI + (size_t)qt * (qt + 1) / 2 + kt) * 4096;
        const float* mk = g_mkt + ((size_t)bh * KT + kt) * QL + q0;
#pragma unroll
        for (int i = 0; i < 4; i++) {
            const int row = ty * 4 + i;
            const int ridx = bh * QL + q0 + row;
            const float lv = g_l[ridx];
            const float sc = (lv > 0.f) ? (__expf(mk[row] - g_m[ridx]) / lv) : 0.f;
            const float4 p = *(const float4*)(ptile + row * 64 + tx * 4);
            *(float4*)(out0 + (size_t)row * KLN + tx * 4) =
                make_float4(p.x * sc, p.y * sc, p.z * sc, p.w * sc);
        }
    }
}

// ---------------------------------------------------------------------------
extern "C" void kernel_launch(void* const* d_in, const int* in_sizes, int n_in,
                              void* d_out, int out_size) {
    (void)in_sizes; (void)n_in;
    const float* q  = (const float*)d_in[0];
    const float* k  = (const float*)d_in[1];
    const float* v  = (const float*)d_in[2];
    const float* Wq = (const float*)d_in[5];
    const float* Wk = (const float*)d_in[6];
    const float* Wv = (const float*)d_in[7];
    const float* Wo = (const float*)d_in[8];

    float* out  = (float*)d_out;
    float* attn = out + (size_t)EL_A;
    const int do_attn = out_size > (int)((size_t)EL_A);

    float *pQ, *pK, *pV;
    cudaGetSymbolAddress((void**)&pQ, g_Qp);
    cudaGetSymbolAddress((void**)&pK, g_Kp);
    cudaGetSymbolAddress((void**)&pV, g_Vp);

    cudaFuncSetAttribute(gemm3, cudaFuncAttributeMaxDynamicSharedMemorySize, NSTG * STG);
    cudaFuncSetAttribute(gemm_wo_pass2, cudaFuncAttributeMaxDynamicSharedMemorySize, NSTG * STG);

    split_all<<<14336, 256>>>(q, k, v, Wq, Wk, Wv, Wo);
    gemm3<<<dim3(8, 64, 3), 512, NSTG * STG>>>(pQ, pK, pV);
    attn_pass1<<<dim3(QT, BB * NH), 256>>>();
    gemm_wo_pass2<<<512 + 16384, 512, NSTG * STG>>>(out, attn, do_attn);
}

// round 16
// speedup vs baseline: 1.1219x; 1.1219x over previous
#include <cuda_runtime.h>
#include <cuda_bf16.h>

// Problem constants
#define QL  2048
#define KLN 2048
#define DM  1024
#define NH  16
#define BB  4
#define QT  32
#define KT  32
#define NTRI 528                 // lower-triangle 64x64 tiles per (b,h)
#define EL_A (BB * QL * DM)      // 8388608
#define GRP_A (EL_A / 8)         // 1048576 = 1<<20
#define EL_W (DM * DM)           // 1048576
#define GRP_W (EL_W / 8)         // 131072 = 1<<17

// Static device scratch (no cudaMalloc allowed)
__device__ float g_Qp[(size_t)EL_A];
__device__ float g_Kp[(size_t)EL_A];
__device__ float g_Vp[(size_t)EL_A];
__device__ float g_m[BB * NH * QL];
__device__ float g_l[BB * NH * QL];
__device__ float g_P[(size_t)BB * NH * NTRI * 4096];   // per-tile exp(s - m_kt)
__device__ float g_mkt[(size_t)BB * NH * KT * QL];     // running max after tile kt
// split-bf16 operand buffers
__device__ __nv_bfloat16 g_Ah[(size_t)3 * EL_A];       // q,k,v hi
__device__ __nv_bfloat16 g_Al[(size_t)3 * EL_A];       // q,k,v lo
__device__ __nv_bfloat16 g_Oh[(size_t)EL_A];           // attn-O hi (from pass1)
__device__ __nv_bfloat16 g_Ol[(size_t)EL_A];           // attn-O lo
__device__ __nv_bfloat16 g_Wh[(size_t)4 * EL_W];       // Wq,Wk,Wv,Wo hi
__device__ __nv_bfloat16 g_Wl[(size_t)4 * EL_W];       // lo

// ---------------------------------------------------------------------------
// Helpers (base-ISA only — toolchain lowers via compute_103, no 'a' features)
// ---------------------------------------------------------------------------
__device__ __forceinline__ unsigned smem_u32(const void* p) {
    unsigned a;
    asm("{ .reg .u64 t; cvta.to.shared.u64 t, %1; cvt.u32.u64 %0, t; }" : "=r"(a) : "l"(p));
    return a;
}
__device__ __forceinline__ float2 ffma2(float2 a, float2 b, float2 c) {
    union U { float2 f; unsigned long long u; } A, B, C;
    A.f = a; B.f = b; C.f = c;
    asm("fma.rn.f32x2 %0, %1, %2, %0;" : "+l"(C.u) : "l"(A.u), "l"(B.u));
    return C.f;
}
__device__ __forceinline__ void ldsm4(unsigned& r0, unsigned& r1, unsigned& r2,
                                      unsigned& r3, unsigned addr) {
    asm volatile("ldmatrix.sync.aligned.m8n8.x4.shared.b16 {%0,%1,%2,%3}, [%4];"
                 : "=r"(r0), "=r"(r1), "=r"(r2), "=r"(r3) : "r"(addr));
}
__device__ __forceinline__ void mma16816(float* c, const unsigned* a,
                                         unsigned b0, unsigned b1) {
    asm volatile(
        "mma.sync.aligned.m16n8k16.row.col.f32.bf16.bf16.f32 "
        "{%0,%1,%2,%3}, {%4,%5,%6,%7}, {%8,%9}, {%0,%1,%2,%3};"
        : "+f"(c[0]), "+f"(c[1]), "+f"(c[2]), "+f"(c[3])
        : "r"(a[0]), "r"(a[1]), "r"(a[2]), "r"(a[3]), "r"(b0), "r"(b1));
}
__device__ __forceinline__ void cp16(unsigned dst, const void* src) {
    asm volatile("cp.async.cg.shared.global [%0], [%1], 16;"
                 :: "r"(dst), "l"(src) : "memory");
}
#define CP_COMMIT() asm volatile("cp.async.commit_group;" ::: "memory")
#define CP_WAIT1()  asm volatile("cp.async.wait_group 1;" ::: "memory")

// ---------------------------------------------------------------------------
// split_all: one kernel splits q,k,v (3 x 8M elems) and 4 W (1M elems each)
// into bf16 hi/lo. grid = 14336 x 256.
// ---------------------------------------------------------------------------
__global__ void __launch_bounds__(256) split_all(
    const float* __restrict__ q, const float* __restrict__ k, const float* __restrict__ v,
    const float* __restrict__ Wq, const float* __restrict__ Wk,
    const float* __restrict__ Wv, const float* __restrict__ Wo) {
    const int i = blockIdx.x * 256 + threadIdx.x;
    const float* src;
    __nv_bfloat16 *hi, *lo;
    size_t off;
    if (i < 3 * GRP_A) {
        const int a = i >> 20;
        off = (size_t)(i & (GRP_A - 1)) * 8;
        src = (a == 0) ? q : (a == 1) ? k : v;
        hi = g_Ah + (size_t)a * EL_A;
        lo = g_Al + (size_t)a * EL_A;
    } else {
        const int j = i - 3 * GRP_A;
        if (j >= 4 * GRP_W) return;
        const int w = j >> 17;
        off = (size_t)(j & (GRP_W - 1)) * 8;
        src = (w == 0) ? Wq : (w == 1) ? Wk : (w == 2) ? Wv : Wo;
        hi = g_Wh + (size_t)w * EL_W;
        lo = g_Wl + (size_t)w * EL_W;
    }
    const float4 a4 = *(const float4*)(src + off);
    const float4 b4 = *(const float4*)(src + off + 4);
    float v8[8] = {a4.x, a4.y, a4.z, a4.w, b4.x, b4.y, b4.z, b4.w};
    __align__(16) __nv_bfloat16 h[8], l[8];
#pragma unroll
    for (int u = 0; u < 8; u++) {
        h[u] = __float2bfloat16(v8[u]);
        l[u] = __float2bfloat16(v8[u] - __bfloat162float(h[u]));
    }
    *(uint4*)(hi + off) = *(const uint4*)h;
    *(uint4*)(lo + off) = *(const uint4*)l;
}

// ---------------------------------------------------------------------------
// Split-bf16 GEMM body (mma.sync + cp.async 3-stage). CTA 128x128, BK=32,
// 16 warps (warp tile 32x32), 512 threads, 96KB dynamic smem.
// C[m0..+128, n0..+128] = A @ W^T, 3 terms Ah*Bh + Ah*Bl + Al*Bh.
// ---------------------------------------------------------------------------
#define T_AH 0
#define T_AL 8192
#define T_BH 16384
#define T_BL 24576
#define STG  32768
#define NSTG 3

__device__ __forceinline__ void gemm_body(
    const __nv_bfloat16* __restrict__ Ahi, const __nv_bfloat16* __restrict__ Alo,
    const __nv_bfloat16* __restrict__ Bhi, const __nv_bfloat16* __restrict__ Blo,
    float* __restrict__ C, int m0, int n0, unsigned smb) {
    const int tid = threadIdx.x, lane = tid & 31, wid = tid >> 5;
    const int wm = wid & 3, wn = wid >> 2;           // warp tile: 32 m x 32 n

    const int lrow = tid >> 2;                        // 0..127
    const int lu0  = tid & 3;                         // unit 0..3
    const __nv_bfloat16* gsrc[4] = {
        Ahi + (size_t)(m0 + lrow) * 1024 + lu0 * 8,
        Alo + (size_t)(m0 + lrow) * 1024 + lu0 * 8,
        Bhi + (size_t)(n0 + lrow) * 1024 + lu0 * 8,
        Blo + (size_t)(n0 + lrow) * 1024 + lu0 * 8};
    const int swr = (lrow >> 1) & 3;
    const unsigned st0 = (unsigned)(lrow * 64 + (lu0 ^ swr) * 16);

    const int rA   = wm * 32 + (lane & 7) + 8 * ((lane >> 3) & 1);
    const int selA = (lane >> 4) & 1;
    const int rB   = wn * 32 + (lane & 7) + 8 * ((lane >> 4) & 1);
    const int selB = (lane >> 3) & 1;
    unsigned offA[2]; int swA[2];
#pragma unroll
    for (int mt = 0; mt < 2; mt++) {
        const int row = rA + mt * 16;
        offA[mt] = row * 64;  swA[mt] = (row >> 1) & 3;
    }
    unsigned offB[2]; int swB[2];
#pragma unroll
    for (int p = 0; p < 2; p++) {
        const int row = rB + p * 16;
        offB[p] = row * 64;  swB[p] = (row >> 1) & 3;
    }

    float acc[2][4][4];
#pragma unroll
    for (int mt = 0; mt < 2; mt++)
#pragma unroll
        for (int nt = 0; nt < 4; nt++)
#pragma unroll
            for (int r = 0; r < 4; r++) acc[mt][nt][r] = 0.f;

#define G_ISSUE(slot, c) do { \
    const unsigned base_ = smb + (slot) * STG; \
    _Pragma("unroll") \
    for (int t = 0; t < 4; t++) \
        cp16(base_ + t * 8192 + st0, gsrc[t] + (c) * 32); \
    } while (0)

    G_ISSUE(0, 0); CP_COMMIT();
    G_ISSUE(1, 1); CP_COMMIT();

    for (int c = 0; c < 32; c++) {
        CP_WAIT1();
        __syncthreads();
        if (c + 2 < 32) G_ISSUE((c + 2) % NSTG, c + 2);
        CP_COMMIT();
        const unsigned sb = smb + (c % NSTG) * STG;
#pragma unroll
        for (int ks = 0; ks < 2; ks++) {
            unsigned ah[2][4], al[2][4];
#pragma unroll
            for (int mt = 0; mt < 2; mt++) {
                const unsigned ua = (unsigned)(((ks * 2 + selA) ^ swA[mt]) * 16);
                ldsm4(ah[mt][0], ah[mt][1], ah[mt][2], ah[mt][3], sb + T_AH + offA[mt] + ua);
                ldsm4(al[mt][0], al[mt][1], al[mt][2], al[mt][3], sb + T_AL + offA[mt] + ua);
            }
            unsigned bh[2][4], bl[2][4];
#pragma unroll
            for (int p = 0; p < 2; p++) {
                const unsigned ub = (unsigned)(((ks * 2 + selB) ^ swB[p]) * 16);
                ldsm4(bh[p][0], bh[p][1], bh[p][2], bh[p][3], sb + T_BH + offB[p] + ub);
                ldsm4(bl[p][0], bl[p][1], bl[p][2], bl[p][3], sb + T_BL + offB[p] + ub);
            }
#pragma unroll
            for (int mt = 0; mt < 2; mt++)
#pragma unroll
                for (int nt = 0; nt < 4; nt++) {
                    const int p = nt >> 1, q = (nt & 1) * 2;
                    mma16816(acc[mt][nt], ah[mt], bh[p][q], bh[p][q + 1]);
                    mma16816(acc[mt][nt], ah[mt], bl[p][q], bl[p][q + 1]);
                    mma16816(acc[mt][nt], al[mt], bh[p][q], bh[p][q + 1]);
                }
        }
    }
#undef G_ISSUE

#pragma unroll
    for (int mt = 0; mt < 2; mt++)
#pragma unroll
        for (int nt = 0; nt < 4; nt++) {
            const int row = m0 + wm * 32 + mt * 16 + (lane >> 2);
            const int col = n0 + wn * 32 + nt * 8 + (lane & 3) * 2;
            *(float2*)(C + (size_t)row * 1024 + col) =
                make_float2(acc[mt][nt][0], acc[mt][nt][1]);
            *(float2*)(C + (size_t)(row + 8) * 1024 + col) =
                make_float2(acc[mt][nt][2], acc[mt][nt][3]);
        }
}

// ---------------------------------------------------------------------------
// gemm3: all three projections in one launch. grid = (8, 64, 3), 512 thr.
// ---------------------------------------------------------------------------
__global__ void __launch_bounds__(512) gemm3(
    float* __restrict__ pQ, float* __restrict__ pK, float* __restrict__ pV) {
    extern __shared__ char sm[];
    const unsigned smb = smem_u32(sm);
    const int z = blockIdx.z;
    float* C = (z == 0) ? pQ : (z == 1) ? pK : pV;
    gemm_body(g_Ah + (size_t)z * EL_A, g_Al + (size_t)z * EL_A,
              g_Wh + (size_t)z * EL_W, g_Wl + (size_t)z * EL_W,
              C, blockIdx.y * 128, blockIdx.x * 128, smb);
}

// ---------------------------------------------------------------------------
// gemm_wo: final projection out = O @ Wo^T. grid = (8, 64), 512 thr.
// ---------------------------------------------------------------------------
__global__ void __launch_bounds__(512) gemm_wo(float* __restrict__ out) {
    extern __shared__ char sm[];
    const unsigned smb = smem_u32(sm);
    gemm_body(g_Oh, g_Ol, g_Wh + (size_t)3 * EL_W, g_Wl + (size_t)3 * EL_W,
              out, blockIdx.y * 128, blockIdx.x * 128, smb);
}

// ---------------------------------------------------------------------------
// Pass 1: causal flash attention (R13-proven inner loops). Streams
// p = exp(s - m_kt) to g_P, m_kt to g_mkt; epilogue writes the bf16 hi/lo
// split of normalized O directly (feeds gemm_wo).
// ---------------------------------------------------------------------------
__global__ void __launch_bounds__(256) attn_pass1() {
    __shared__ float Qs[64 * 64];
    __shared__ float KV[64 * 64];
    __shared__ float Ps[64 * 64];
    const int tid = threadIdx.x;
    const int tx = tid & 15, ty = tid >> 4;
    const int qt = blockIdx.x;
    const int bh = blockIdx.y;
    const int b = bh >> 4, h = bh & 15;
    const int q0 = qt * 64;

    {
        const int f = tid & 15, r0 = tid >> 4;
#pragma unroll
        for (int rr = 0; rr < 4; rr++) {
            const int r = r0 + rr * 16;
            *(float4*)&Qs[r * 64 + f * 4] =
                *(const float4*)(g_Qp + (size_t)(b * QL + q0 + r) * DM + h * 64 + f * 4);
        }
    }
    float2 Oacc[4][2];
#pragma unroll
    for (int i = 0; i < 4; i++) { Oacc[i][0] = make_float2(0.f, 0.f); Oacc[i][1] = make_float2(0.f, 0.f); }
    float mrow[4], lrow[4];
#pragma unroll
    for (int i = 0; i < 4; i++) { mrow[i] = -1e30f; lrow[i] = 0.f; }

    for (int kt = 0; kt <= qt; kt++) {
        const int k0 = kt * 64;
        const bool diag = (kt == qt);
        __syncthreads();
        {   // load K tile transposed: KV[d][c]
            const int c = tid & 63, dq = tid >> 6;
            const float* kg = g_Kp + (size_t)(b * KLN + k0 + c) * DM + h * 64 + dq * 16;
            float4 vv[4];
            vv[0] = *(const float4*)(kg + 0);  vv[1] = *(const float4*)(kg + 4);
            vv[2] = *(const float4*)(kg + 8);  vv[3] = *(const float4*)(kg + 12);
            const float* vp = (const float*)vv;
#pragma unroll
            for (int u = 0; u < 16; u++) KV[(dq * 16 + u) * 64 + c] = vp[u];
        }
        __syncthreads();
        float2 S[4][2];
#pragma unroll
        for (int i = 0; i < 4; i++) { S[i][0] = make_float2(0.f, 0.f); S[i][1] = make_float2(0.f, 0.f); }
#pragma unroll 8
        for (int d = 0; d < 64; d++) {
            const float2 b0 = *(const float2*)&KV[d * 64 + tx * 4];
            const float2 b1 = *(const float2*)&KV[d * 64 + tx * 4 + 2];
#pragma unroll
            for (int i = 0; i < 4; i++) {
                const float a = Qs[(ty * 4 + i) * 64 + d];
                const float2 ap = make_float2(a, a);
                S[i][0] = ffma2(ap, b0, S[i][0]);
                S[i][1] = ffma2(ap, b1, S[i][1]);
            }
        }
        __syncthreads();                              // K reads done; reuse KV for V
        {   // load V tile natural: KV[c][d]
            const int f = tid & 15, c0 = tid >> 4;
#pragma unroll
            for (int rr = 0; rr < 4; rr++) {
                const int c = c0 + rr * 16;
                *(float4*)&KV[c * 64 + f * 4] =
                    *(const float4*)(g_Vp + (size_t)(b * KLN + k0 + c) * DM + h * 64 + f * 4);
            }
        }
        float sv[4][4];
#pragma unroll
        for (int i = 0; i < 4; i++) {
            sv[i][0] = S[i][0].x * 0.125f;  sv[i][1] = S[i][0].y * 0.125f;
            sv[i][2] = S[i][1].x * 0.125f;  sv[i][3] = S[i][1].y * 0.125f;
        }
        if (diag) {
#pragma unroll
            for (int i = 0; i < 4; i++)
#pragma unroll
                for (int j = 0; j < 4; j++)
                    if (tx * 4 + j > ty * 4 + i) sv[i][j] = -1e30f;
        }
        float* ptile = g_P + ((size_t)bh * NTRI + (size_t)qt * (qt + 1) / 2 + kt) * 4096;
#pragma unroll
        for (int i = 0; i < 4; i++) {
            float tm = fmaxf(fmaxf(sv[i][0], sv[i][1]), fmaxf(sv[i][2], sv[i][3]));
#pragma unroll
            for (int m = 8; m >= 1; m >>= 1) tm = fmaxf(tm, __shfl_xor_sync(0xffffffffu, tm, m));
            const float mn = fmaxf(mrow[i], tm);
            const float alpha = __expf(mrow[i] - mn);
            mrow[i] = mn;
            float p[4];
#pragma unroll
            for (int j = 0; j < 4; j++)
                p[j] = (sv[i][j] <= -1e29f) ? 0.f : __expf(sv[i][j] - mn);
            float rs = p[0] + p[1] + p[2] + p[3];
#pragma unroll
            for (int m = 8; m >= 1; m >>= 1) rs += __shfl_xor_sync(0xffffffffu, rs, m);
            lrow[i] = lrow[i] * alpha + rs;
            Oacc[i][0].x *= alpha; Oacc[i][0].y *= alpha;
            Oacc[i][1].x *= alpha; Oacc[i][1].y *= alpha;
            *(float2*)&Ps[(ty * 4 + i) * 64 + tx * 4]     = make_float2(p[0], p[1]);
            *(float2*)&Ps[(ty * 4 + i) * 64 + tx * 4 + 2] = make_float2(p[2], p[3]);
            *(float4*)(ptile + (ty * 4 + i) * 64 + tx * 4) =
                make_float4(p[0], p[1], p[2], p[3]);
        }
        if (tx == 0) {
            float* mk = g_mkt + ((size_t)bh * KT + kt) * QL + q0;
#pragma unroll
            for (int i = 0; i < 4; i++) mk[ty * 4 + i] = mrow[i];
        }
        __syncthreads();                              // V + P staged
#pragma unroll 8
        for (int c = 0; c < 64; c++) {
            const float2 b0 = *(const float2*)&KV[c * 64 + tx * 4];
            const float2 b1 = *(const float2*)&KV[c * 64 + tx * 4 + 2];
#pragma unroll
            for (int i = 0; i < 4; i++) {
                const float a = Ps[(ty * 4 + i) * 64 + c];
                const float2 ap = make_float2(a, a);
                Oacc[i][0] = ffma2(ap, b0, Oacc[i][0]);
                Oacc[i][1] = ffma2(ap, b1, Oacc[i][1]);
            }
        }
    }
    // epilogue: normalize, write O directly as bf16 hi/lo split + save (m, l)
#pragma unroll
    for (int i = 0; i < 4; i++) {
        const float inv = (lrow[i] > 0.f) ? (1.f / lrow[i]) : 0.f;
        const float o[4] = {Oacc[i][0].x * inv, Oacc[i][0].y * inv,
                            Oacc[i][1].x * inv, Oacc[i][1].y * inv};
        __align__(8) __nv_bfloat16 h4[4], l4[4];
#pragma unroll
        for (int u = 0; u < 4; u++) {
            h4[u] = __float2bfloat16(o[u]);
            l4[u] = __float2bfloat16(o[u] - __bfloat162float(h4[u]));
        }
        const size_t idx = (size_t)(b * QL + q0 + ty * 4 + i) * DM + h * 64 + tx * 4;
        *(uint2*)(g_Oh + idx) = *(const uint2*)h4;
        *(uint2*)(g_Ol + idx) = *(const uint2*)l4;
    }
    if (tx == 0) {
#pragma unroll
        for (int i = 0; i < 4; i++) {
            const int idx = bh * QL + q0 + ty * 4 + i;
            g_m[idx] = mrow[i];
            g_l[idx] = lrow[i];
        }
    }
}

// ---------------------------------------------------------------------------
// Pass 2: attn = g_P * exp(m_kt - m_final) / l  (pure rescale+store).
// grid = (KT, QT, B*H), 256 threads, zero smem -> full occupancy.
// ---------------------------------------------------------------------------
__global__ void __launch_bounds__(256) attn_pass2(float* __restrict__ attn) {
    const int tid = threadIdx.x;
    const int tx = tid & 15, ty = tid >> 4;
    const int kt = blockIdx.x, qt = blockIdx.y, bh = blockIdx.z;
    const int q0 = qt * 64, k0 = kt * 64;
    float* out0 = attn + ((size_t)bh * QL + q0) * KLN + k0;

    if (kt > qt) {
        const int f = tid & 15, r0 = tid >> 4;
        const float4 z = make_float4(0.f, 0.f, 0.f, 0.f);
#pragma unroll
        for (int rr = 0; rr < 4; rr++)
            *(float4*)(out0 + (size_t)(r0 + rr * 16) * KLN + f * 4) = z;
        return;
    }
    const float* ptile = g_P + ((size_t)bh * NTRI + (size_t)qt * (qt + 1) / 2 + kt) * 4096;
    const float* mk = g_mkt + ((size_t)bh * KT + kt) * QL + q0;
#pragma unroll
    for (int i = 0; i < 4; i++) {
        const int row = ty * 4 + i;
        const int ridx = bh * QL + q0 + row;
        const float lv = g_l[ridx];
        const float sc = (lv > 0.f) ? (__expf(mk[row] - g_m[ridx]) / lv) : 0.f;
        const float4 p = *(const float4*)(ptile + row * 64 + tx * 4);
        *(float4*)(out0 + (size_t)row * KLN + tx * 4) =
            make_float4(p.x * sc, p.y * sc, p.z * sc, p.w * sc);
    }
}

// ---------------------------------------------------------------------------
extern "C" void kernel_launch(void* const* d_in, const int* in_sizes, int n_in,
                              void* d_out, int out_size) {
    (void)in_sizes; (void)n_in;
    const float* q  = (const float*)d_in[0];
    const float* k  = (const float*)d_in[1];
    const float* v  = (const float*)d_in[2];
    const float* Wq = (const float*)d_in[5];
    const float* Wk = (const float*)d_in[6];
    const float* Wv = (const float*)d_in[7];
    const float* Wo = (const float*)d_in[8];

    float* out  = (float*)d_out;
    float* attn = out + (size_t)EL_A;
    const int do_attn = out_size > (int)((size_t)EL_A);

    float *pQ, *pK, *pV;
    cudaGetSymbolAddress((void**)&pQ, g_Qp);
    cudaGetSymbolAddress((void**)&pK, g_Kp);
    cudaGetSymbolAddress((void**)&pV, g_Vp);

    cudaFuncSetAttribute(gemm3, cudaFuncAttributeMaxDynamicSharedMemorySize, NSTG * STG);
    cudaFuncSetAttribute(gemm_wo, cudaFuncAttributeMaxDynamicSharedMemorySize, NSTG * STG);

    // Lazily-created side stream + events for a parallel tail branch in the
    // captured graph (host-side resources only; identical work every call).
    static cudaStream_t s_tail = nullptr;
    static cudaEvent_t ev_fork = nullptr, ev_join = nullptr;
    if (s_tail == nullptr) {
        cudaStreamCreateWithFlags(&s_tail, cudaStreamNonBlocking);
        cudaEventCreateWithFlags(&ev_fork, cudaEventDisableTiming);
        cudaEventCreateWithFlags(&ev_join, cudaEventDisableTiming);
    }

    split_all<<<14336, 256>>>(q, k, v, Wq, Wk, Wv, Wo);
    gemm3<<<dim3(8, 64, 3), 512, NSTG * STG>>>(pQ, pK, pV);
    attn_pass1<<<dim3(QT, BB * NH), 256>>>();

    // fork: pass2 (DRAM-bound, 0 smem) runs parallel to gemm_wo (tensor-bound)
    cudaEventRecord(ev_fork, 0);
    cudaStreamWaitEvent(s_tail, ev_fork, 0);
    if (do_attn)
        attn_pass2<<<dim3(KT, QT, BB * NH), 256, 0, s_tail>>>(attn);
    gemm_wo<<<dim3(8, 64), 512, NSTG * STG>>>(out);
    cudaEventRecord(ev_join, s_tail);
    cudaStreamWaitEvent(0, ev_join, 0);
}

// round 17
// speedup vs baseline: 1.1268x; 1.0043x over previous
#include <cuda_runtime.h>
#include <cuda_bf16.h>

// Problem constants
#define QL  2048
#define KLN 2048
#define DM  1024
#define NH  16
#define BB  4
#define QT  32
#define KT  32
#define NTRI 528                 // lower-triangle 64x64 tiles per (b,h)
#define EL_A (BB * QL * DM)      // 8388608
#define GRP_A (EL_A / 8)         // 1048576 = 1<<20
#define EL_W (DM * DM)           // 1048576
#define GRP_W (EL_W / 8)         // 131072 = 1<<17

// Static device scratch (no cudaMalloc allowed)
__device__ float g_Qp[(size_t)EL_A];
__device__ float g_Kp[(size_t)EL_A];
__device__ float g_Vp[(size_t)EL_A];
__device__ float g_m[BB * NH * QL];
__device__ float g_l[BB * NH * QL];
__device__ float g_P[(size_t)BB * NH * NTRI * 4096];   // per-tile exp(s - m_kt)
__device__ float g_mkt[(size_t)BB * NH * KT * QL];     // running max after tile kt
// split-bf16 operand buffers
__device__ __nv_bfloat16 g_Ah[(size_t)3 * EL_A];       // q,k,v hi
__device__ __nv_bfloat16 g_Al[(size_t)3 * EL_A];       // q,k,v lo
__device__ __nv_bfloat16 g_Oh[(size_t)EL_A];           // attn-O hi (from pass1)
__device__ __nv_bfloat16 g_Ol[(size_t)EL_A];           // attn-O lo
__device__ __nv_bfloat16 g_Wh[(size_t)4 * EL_W];       // Wq,Wk,Wv,Wo hi
__device__ __nv_bfloat16 g_Wl[(size_t)4 * EL_W];       // lo

// ---------------------------------------------------------------------------
// Helpers (base-ISA only — toolchain lowers via compute_103, no 'a' features)
// ---------------------------------------------------------------------------
__device__ __forceinline__ unsigned smem_u32(const void* p) {
    unsigned a;
    asm("{ .reg .u64 t; cvta.to.shared.u64 t, %1; cvt.u32.u64 %0, t; }" : "=r"(a) : "l"(p));
    return a;
}
__device__ __forceinline__ float2 ffma2(float2 a, float2 b, float2 c) {
    union U { float2 f; unsigned long long u; } A, B, C;
    A.f = a; B.f = b; C.f = c;
    asm("fma.rn.f32x2 %0, %1, %2, %0;" : "+l"(C.u) : "l"(A.u), "l"(B.u));
    return C.f;
}
__device__ __forceinline__ void ldsm4(unsigned& r0, unsigned& r1, unsigned& r2,
                                      unsigned& r3, unsigned addr) {
    asm volatile("ldmatrix.sync.aligned.m8n8.x4.shared.b16 {%0,%1,%2,%3}, [%4];"
                 : "=r"(r0), "=r"(r1), "=r"(r2), "=r"(r3) : "r"(addr));
}
__device__ __forceinline__ void mma16816(float* c, const unsigned* a,
                                         unsigned b0, unsigned b1) {
    asm volatile(
        "mma.sync.aligned.m16n8k16.row.col.f32.bf16.bf16.f32 "
        "{%0,%1,%2,%3}, {%4,%5,%6,%7}, {%8,%9}, {%0,%1,%2,%3};"
        : "+f"(c[0]), "+f"(c[1]), "+f"(c[2]), "+f"(c[3])
        : "r"(a[0]), "r"(a[1]), "r"(a[2]), "r"(a[3]), "r"(b0), "r"(b1));
}
__device__ __forceinline__ void cp16(unsigned dst, const void* src) {
    asm volatile("cp.async.cg.shared.global [%0], [%1], 16;"
                 :: "r"(dst), "l"(src) : "memory");
}
#define CP_COMMIT() asm volatile("cp.async.commit_group;" ::: "memory")
#define CP_WAIT1()  asm volatile("cp.async.wait_group 1;" ::: "memory")

// ---------------------------------------------------------------------------
// split_all: one kernel splits q,k,v (3 x 8M elems) and 4 W (1M elems each)
// into bf16 hi/lo. grid = 14336 x 256.
// ---------------------------------------------------------------------------
__global__ void __launch_bounds__(256) split_all(
    const float* __restrict__ q, const float* __restrict__ k, const float* __restrict__ v,
    const float* __restrict__ Wq, const float* __restrict__ Wk,
    const float* __restrict__ Wv, const float* __restrict__ Wo) {
    const int i = blockIdx.x * 256 + threadIdx.x;
    const float* src;
    __nv_bfloat16 *hi, *lo;
    size_t off;
    if (i < 3 * GRP_A) {
        const int a = i >> 20;
        off = (size_t)(i & (GRP_A - 1)) * 8;
        src = (a == 0) ? q : (a == 1) ? k : v;
        hi = g_Ah + (size_t)a * EL_A;
        lo = g_Al + (size_t)a * EL_A;
    } else {
        const int j = i - 3 * GRP_A;
        if (j >= 4 * GRP_W) return;
        const int w = j >> 17;
        off = (size_t)(j & (GRP_W - 1)) * 8;
        src = (w == 0) ? Wq : (w == 1) ? Wk : (w == 2) ? Wv : Wo;
        hi = g_Wh + (size_t)w * EL_W;
        lo = g_Wl + (size_t)w * EL_W;
    }
    const float4 a4 = *(const float4*)(src + off);
    const float4 b4 = *(const float4*)(src + off + 4);
    float v8[8] = {a4.x, a4.y, a4.z, a4.w, b4.x, b4.y, b4.z, b4.w};
    __align__(16) __nv_bfloat16 h[8], l[8];
#pragma unroll
    for (int u = 0; u < 8; u++) {
        h[u] = __float2bfloat16(v8[u]);
        l[u] = __float2bfloat16(v8[u] - __bfloat162float(h[u]));
    }
    *(uint4*)(hi + off) = *(const uint4*)h;
    *(uint4*)(lo + off) = *(const uint4*)l;
}

// ---------------------------------------------------------------------------
// Split-bf16 GEMM body (mma.sync + cp.async 3-stage). CTA 128x128, BK=32,
// 16 warps (warp tile 32x32), 512 threads, 96KB dynamic smem.
// C[m0..+128, n0..+128] = A @ W^T, 3 terms Ah*Bh + Ah*Bl + Al*Bh.
// ---------------------------------------------------------------------------
#define T_AH 0
#define T_AL 8192
#define T_BH 16384
#define T_BL 24576
#define STG  32768
#define NSTG 3

__device__ __forceinline__ void gemm_body(
    const __nv_bfloat16* __restrict__ Ahi, const __nv_bfloat16* __restrict__ Alo,
    const __nv_bfloat16* __restrict__ Bhi, const __nv_bfloat16* __restrict__ Blo,
    float* __restrict__ C, int m0, int n0, unsigned smb) {
    const int tid = threadIdx.x, lane = tid & 31, wid = tid >> 5;
    const int wm = wid & 3, wn = wid >> 2;           // warp tile: 32 m x 32 n

    const int lrow = tid >> 2;                        // 0..127
    const int lu0  = tid & 3;                         // unit 0..3
    const __nv_bfloat16* gsrc[4] = {
        Ahi + (size_t)(m0 + lrow) * 1024 + lu0 * 8,
        Alo + (size_t)(m0 + lrow) * 1024 + lu0 * 8,
        Bhi + (size_t)(n0 + lrow) * 1024 + lu0 * 8,
        Blo + (size_t)(n0 + lrow) * 1024 + lu0 * 8};
    const int swr = (lrow >> 1) & 3;
    const unsigned st0 = (unsigned)(lrow * 64 + (lu0 ^ swr) * 16);

    const int rA   = wm * 32 + (lane & 7) + 8 * ((lane >> 3) & 1);
    const int selA = (lane >> 4) & 1;
    const int rB   = wn * 32 + (lane & 7) + 8 * ((lane >> 4) & 1);
    const int selB = (lane >> 3) & 1;
    unsigned offA[2]; int swA[2];
#pragma unroll
    for (int mt = 0; mt < 2; mt++) {
        const int row = rA + mt * 16;
        offA[mt] = row * 64;  swA[mt] = (row >> 1) & 3;
    }
    unsigned offB[2]; int swB[2];
#pragma unroll
    for (int p = 0; p < 2; p++) {
        const int row = rB + p * 16;
        offB[p] = row * 64;  swB[p] = (row >> 1) & 3;
    }

    float acc[2][4][4];
#pragma unroll
    for (int mt = 0; mt < 2; mt++)
#pragma unroll
        for (int nt = 0; nt < 4; nt++)
#pragma unroll
            for (int r = 0; r < 4; r++) acc[mt][nt][r] = 0.f;

#define G_ISSUE(slot, c) do { \
    const unsigned base_ = smb + (slot) * STG; \
    _Pragma("unroll") \
    for (int t = 0; t < 4; t++) \
        cp16(base_ + t * 8192 + st0, gsrc[t] + (c) * 32); \
    } while (0)

    G_ISSUE(0, 0); CP_COMMIT();
    G_ISSUE(1, 1); CP_COMMIT();

    for (int c = 0; c < 32; c++) {
        CP_WAIT1();
        __syncthreads();
        if (c + 2 < 32) G_ISSUE((c + 2) % NSTG, c + 2);
        CP_COMMIT();
        const unsigned sb = smb + (c % NSTG) * STG;
#pragma unroll
        for (int ks = 0; ks < 2; ks++) {
            unsigned ah[2][4], al[2][4];
#pragma unroll
            for (int mt = 0; mt < 2; mt++) {
                const unsigned ua = (unsigned)(((ks * 2 + selA) ^ swA[mt]) * 16);
                ldsm4(ah[mt][0], ah[mt][1], ah[mt][2], ah[mt][3], sb + T_AH + offA[mt] + ua);
                ldsm4(al[mt][0], al[mt][1], al[mt][2], al[mt][3], sb + T_AL + offA[mt] + ua);
            }
            unsigned bh[2][4], bl[2][4];
#pragma unroll
            for (int p = 0; p < 2; p++) {
                const unsigned ub = (unsigned)(((ks * 2 + selB) ^ swB[p]) * 16);
                ldsm4(bh[p][0], bh[p][1], bh[p][2], bh[p][3], sb + T_BH + offB[p] + ub);
                ldsm4(bl[p][0], bl[p][1], bl[p][2], bl[p][3], sb + T_BL + offB[p] + ub);
            }
#pragma unroll
            for (int mt = 0; mt < 2; mt++)
#pragma unroll
                for (int nt = 0; nt < 4; nt++) {
                    const int p = nt >> 1, q = (nt & 1) * 2;
                    mma16816(acc[mt][nt], ah[mt], bh[p][q], bh[p][q + 1]);
                    mma16816(acc[mt][nt], ah[mt], bl[p][q], bl[p][q + 1]);
                    mma16816(acc[mt][nt], al[mt], bh[p][q], bh[p][q + 1]);
                }
        }
    }
#undef G_ISSUE

#pragma unroll
    for (int mt = 0; mt < 2; mt++)
#pragma unroll
        for (int nt = 0; nt < 4; nt++) {
            const int row = m0 + wm * 32 + mt * 16 + (lane >> 2);
            const int col = n0 + wn * 32 + nt * 8 + (lane & 3) * 2;
            *(float2*)(C + (size_t)row * 1024 + col) =
                make_float2(acc[mt][nt][0], acc[mt][nt][1]);
            *(float2*)(C + (size_t)(row + 8) * 1024 + col) =
                make_float2(acc[mt][nt][2], acc[mt][nt][3]);
        }
}

// ---------------------------------------------------------------------------
// gemm3: all three projections in one launch. grid = (8, 64, 3), 512 thr.
// ---------------------------------------------------------------------------
__global__ void __launch_bounds__(512) gemm3(
    float* __restrict__ pQ, float* __restrict__ pK, float* __restrict__ pV) {
    extern __shared__ char sm[];
    const unsigned smb = smem_u32(sm);
    const int z = blockIdx.z;
    float* C = (z == 0) ? pQ : (z == 1) ? pK : pV;
    gemm_body(g_Ah + (size_t)z * EL_A, g_Al + (size_t)z * EL_A,
              g_Wh + (size_t)z * EL_W, g_Wl + (size_t)z * EL_W,
              C, blockIdx.y * 128, blockIdx.x * 128, smb);
}

// ---------------------------------------------------------------------------
// gemm_wo: final projection out = O @ Wo^T. grid = (8, 64), 512 thr.
// ---------------------------------------------------------------------------
__global__ void __launch_bounds__(512) gemm_wo(float* __restrict__ out) {
    extern __shared__ char sm[];
    const unsigned smb = smem_u32(sm);
    gemm_body(g_Oh, g_Ol, g_Wh + (size_t)3 * EL_W, g_Wl + (size_t)3 * EL_W,
              out, blockIdx.y * 128, blockIdx.x * 128, smb);
}

// ---------------------------------------------------------------------------
// Pass 1: causal flash attention. float4 inner loops (half the smem
// wavefronts of the scalar form; identical FMA order -> identical numerics).
// Streams p = exp(s - m_kt) to g_P, m_kt to g_mkt; epilogue writes the bf16
// hi/lo split of normalized O directly (feeds gemm_wo).
// ---------------------------------------------------------------------------
__global__ void __launch_bounds__(256) attn_pass1() {
    __shared__ float Qs[64 * 64];
    __shared__ float KV[64 * 64];
    __shared__ float Ps[64 * 64];
    const int tid = threadIdx.x;
    const int tx = tid & 15, ty = tid >> 4;
    const int qt = blockIdx.x;
    const int bh = blockIdx.y;
    const int b = bh >> 4, h = bh & 15;
    const int q0 = qt * 64;

    {
        const int f = tid & 15, r0 = tid >> 4;
#pragma unroll
        for (int rr = 0; rr < 4; rr++) {
            const int r = r0 + rr * 16;
            *(float4*)&Qs[r * 64 + f * 4] =
                *(const float4*)(g_Qp + (size_t)(b * QL + q0 + r) * DM + h * 64 + f * 4);
        }
    }
    float2 Oacc[4][2];
#pragma unroll
    for (int i = 0; i < 4; i++) { Oacc[i][0] = make_float2(0.f, 0.f); Oacc[i][1] = make_float2(0.f, 0.f); }
    float mrow[4], lrow[4];
#pragma unroll
    for (int i = 0; i < 4; i++) { mrow[i] = -1e30f; lrow[i] = 0.f; }

    for (int kt = 0; kt <= qt; kt++) {
        const int k0 = kt * 64;
        const bool diag = (kt == qt);
        __syncthreads();
        {   // load K tile transposed: KV[d][c]
            const int c = tid & 63, dq = tid >> 6;
            const float* kg = g_Kp + (size_t)(b * KLN + k0 + c) * DM + h * 64 + dq * 16;
            float4 vv[4];
            vv[0] = *(const float4*)(kg + 0);  vv[1] = *(const float4*)(kg + 4);
            vv[2] = *(const float4*)(kg + 8);  vv[3] = *(const float4*)(kg + 12);
            const float* vp = (const float*)vv;
#pragma unroll
            for (int u = 0; u < 16; u++) KV[(dq * 16 + u) * 64 + c] = vp[u];
        }
        __syncthreads();
        // S = Q @ K^T : 4-step d, float4 LDS (same accumulation order)
        float2 S[4][2];
#pragma unroll
        for (int i = 0; i < 4; i++) { S[i][0] = make_float2(0.f, 0.f); S[i][1] = make_float2(0.f, 0.f); }
#pragma unroll 4
        for (int d4 = 0; d4 < 64; d4 += 4) {
            float4 bv[4], av[4];
#pragma unroll
            for (int u = 0; u < 4; u++) bv[u] = *(const float4*)&KV[(d4 + u) * 64 + tx * 4];
#pragma unroll
            for (int i = 0; i < 4; i++) av[i] = *(const float4*)&Qs[(ty * 4 + i) * 64 + d4];
#pragma unroll
            for (int u = 0; u < 4; u++) {
                const float2 b0 = make_float2(bv[u].x, bv[u].y);
                const float2 b1 = make_float2(bv[u].z, bv[u].w);
#pragma unroll
                for (int i = 0; i < 4; i++) {
                    const float a = (u == 0) ? av[i].x : (u == 1) ? av[i].y
                                  : (u == 2) ? av[i].z : av[i].w;
                    const float2 ap = make_float2(a, a);
                    S[i][0] = ffma2(ap, b0, S[i][0]);
                    S[i][1] = ffma2(ap, b1, S[i][1]);
                }
            }
        }
        __syncthreads();                              // K reads done; reuse KV for V
        {   // load V tile natural: KV[c][d]
            const int f = tid & 15, c0 = tid >> 4;
#pragma unroll
            for (int rr = 0; rr < 4; rr++) {
                const int c = c0 + rr * 16;
                *(float4*)&KV[c * 64 + f * 4] =
                    *(const float4*)(g_Vp + (size_t)(b * KLN + k0 + c) * DM + h * 64 + f * 4);
            }
        }
        float sv[4][4];
#pragma unroll
        for (int i = 0; i < 4; i++) {
            sv[i][0] = S[i][0].x * 0.125f;  sv[i][1] = S[i][0].y * 0.125f;
            sv[i][2] = S[i][1].x * 0.125f;  sv[i][3] = S[i][1].y * 0.125f;
        }
        if (diag) {
#pragma unroll
            for (int i = 0; i < 4; i++)
#pragma unroll
                for (int j = 0; j < 4; j++)
                    if (tx * 4 + j > ty * 4 + i) sv[i][j] = -1e30f;
        }
        float* ptile = g_P + ((size_t)bh * NTRI + (size_t)qt * (qt + 1) / 2 + kt) * 4096;
#pragma unroll
        for (int i = 0; i < 4; i++) {
            float tm = fmaxf(fmaxf(sv[i][0], sv[i][1]), fmaxf(sv[i][2], sv[i][3]));
#pragma unroll
            for (int m = 8; m >= 1; m >>= 1) tm = fmaxf(tm, __shfl_xor_sync(0xffffffffu, tm, m));
            const float mn = fmaxf(mrow[i], tm);
            const float alpha = __expf(mrow[i] - mn);
            mrow[i] = mn;
            float p[4];
#pragma unroll
            for (int j = 0; j < 4; j++)
                p[j] = (sv[i][j] <= -1e29f) ? 0.f : __expf(sv[i][j] - mn);
            float rs = p[0] + p[1] + p[2] + p[3];
#pragma unroll
            for (int m = 8; m >= 1; m >>= 1) rs += __shfl_xor_sync(0xffffffffu, rs, m);
            lrow[i] = lrow[i] * alpha + rs;
            Oacc[i][0].x *= alpha; Oacc[i][0].y *= alpha;
            Oacc[i][1].x *= alpha; Oacc[i][1].y *= alpha;
            *(float2*)&Ps[(ty * 4 + i) * 64 + tx * 4]     = make_float2(p[0], p[1]);
            *(float2*)&Ps[(ty * 4 + i) * 64 + tx * 4 + 2] = make_float2(p[2], p[3]);
            *(float4*)(ptile + (ty * 4 + i) * 64 + tx * 4) =
                make_float4(p[0], p[1], p[2], p[3]);
        }
        if (tx == 0) {
            float* mk = g_mkt + ((size_t)bh * KT + kt) * QL + q0;
#pragma unroll
            for (int i = 0; i < 4; i++) mk[ty * 4 + i] = mrow[i];
        }
        __syncthreads();                              // V + P staged
        // O += P @ V : 4-step c, float4 LDS (same accumulation order)
#pragma unroll 4
        for (int c4 = 0; c4 < 64; c4 += 4) {
            float4 bv[4], av[4];
#pragma unroll
            for (int u = 0; u < 4; u++) bv[u] = *(const float4*)&KV[(c4 + u) * 64 + tx * 4];
#pragma unroll
            for (int i = 0; i < 4; i++) av[i] = *(const float4*)&Ps[(ty * 4 + i) * 64 + c4];
#pragma unroll
            for (int u = 0; u < 4; u++) {
                const float2 b0 = make_float2(bv[u].x, bv[u].y);
                const float2 b1 = make_float2(bv[u].z, bv[u].w);
#pragma unroll
                for (int i = 0; i < 4; i++) {
                    const float a = (u == 0) ? av[i].x : (u == 1) ? av[i].y
                                  : (u == 2) ? av[i].z : av[i].w;
                    const float2 ap = make_float2(a, a);
                    Oacc[i][0] = ffma2(ap, b0, Oacc[i][0]);
                    Oacc[i][1] = ffma2(ap, b1, Oacc[i][1]);
                }
            }
        }
    }
    // epilogue: normalize, write O directly as bf16 hi/lo split + save (m, l)
#pragma unroll
    for (int i = 0; i < 4; i++) {
        const float inv = (lrow[i] > 0.f) ? (1.f / lrow[i]) : 0.f;
        const float o[4] = {Oacc[i][0].x * inv, Oacc[i][0].y * inv,
                            Oacc[i][1].x * inv, Oacc[i][1].y * inv};
        __align__(8) __nv_bfloat16 h4[4], l4[4];
#pragma unroll
        for (int u = 0; u < 4; u++) {
            h4[u] = __float2bfloat16(o[u]);
            l4[u] = __float2bfloat16(o[u] - __bfloat162float(h4[u]));
        }
        const size_t idx = (size_t)(b * QL + q0 + ty * 4 + i) * DM + h * 64 + tx * 4;
        *(uint2*)(g_Oh + idx) = *(const uint2*)h4;
        *(uint2*)(g_Ol + idx) = *(const uint2*)l4;
    }
    if (tx == 0) {
#pragma unroll
        for (int i = 0; i < 4; i++) {
            const int idx = bh * QL + q0 + ty * 4 + i;
            g_m[idx] = mrow[i];
            g_l[idx] = lrow[i];
        }
    }
}

// ---------------------------------------------------------------------------
// Pass 2: attn = g_P * exp(m_kt - m_final) / l  (pure rescale+store).
// grid = (KT, QT, B*H), 256 threads, zero smem -> full occupancy.
// ---------------------------------------------------------------------------
__global__ void __launch_bounds__(256) attn_pass2(float* __restrict__ attn) {
    const int tid = threadIdx.x;
    const int tx = tid & 15, ty = tid >> 4;
    const int kt = blockIdx.x, qt = blockIdx.y, bh = blockIdx.z;
    const int q0 = qt * 64, k0 = kt * 64;
    float* out0 = attn + ((size_t)bh * QL + q0) * KLN + k0;

    if (kt > qt) {
        const int f = tid & 15, r0 = tid >> 4;
        const float4 z = make_float4(0.f, 0.f, 0.f, 0.f);
#pragma unroll
        for (int rr = 0; rr < 4; rr++)
            *(float4*)(out0 + (size_t)(r0 + rr * 16) * KLN + f * 4) = z;
        return;
    }
    const float* ptile = g_P + ((size_t)bh * NTRI + (size_t)qt * (qt + 1) / 2 + kt) * 4096;
    const float* mk = g_mkt + ((size_t)bh * KT + kt) * QL + q0;
#pragma unroll
    for (int i = 0; i < 4; i++) {
        const int row = ty * 4 + i;
        const int ridx = bh * QL + q0 + row;
        const float lv = g_l[ridx];
        const float sc = (lv > 0.f) ? (__expf(mk[row] - g_m[ridx]) / lv) : 0.f;
        const float4 p = *(const float4*)(ptile + row * 64 + tx * 4);
        *(float4*)(out0 + (size_t)row * KLN + tx * 4) =
            make_float4(p.x * sc, p.y * sc, p.z * sc, p.w * sc);
    }
}

// ---------------------------------------------------------------------------
extern "C" void kernel_launch(void* const* d_in, const int* in_sizes, int n_in,
                              void* d_out, int out_size) {
    (void)in_sizes; (void)n_in;
    const float* q  = (const float*)d_in[0];
    const float* k  = (const float*)d_in[1];
    const float* v  = (const float*)d_in[2];
    const float* Wq = (const float*)d_in[5];
    const float* Wk = (const float*)d_in[6];
    const float* Wv = (const float*)d_in[7];
    const float* Wo = (const float*)d_in[8];

    float* out  = (float*)d_out;
    float* attn = out + (size_t)EL_A;
    const int do_attn = out_size > (int)((size_t)EL_A);

    float *pQ, *pK, *pV;
    cudaGetSymbolAddress((void**)&pQ, g_Qp);
    cudaGetSymbolAddress((void**)&pK, g_Kp);
    cudaGetSymbolAddress((void**)&pV, g_Vp);

    cudaFuncSetAttribute(gemm3, cudaFuncAttributeMaxDynamicSharedMemorySize, NSTG * STG);
    cudaFuncSetAttribute(gemm_wo, cudaFuncAttributeMaxDynamicSharedMemorySize, NSTG * STG);

    // Lazily-created side stream + events for a parallel tail branch in the
    // captured graph (host-side resources only; identical work every call).
    static cudaStream_t s_tail = nullptr;
    static cudaEvent_t ev_fork = nullptr, ev_join = nullptr;
    if (s_tail == nullptr) {
        cudaStreamCreateWithFlags(&s_tail, cudaStreamNonBlocking);
        cudaEventCreateWithFlags(&ev_fork, cudaEventDisableTiming);
        cudaEventCreateWithFlags(&ev_join, cudaEventDisableTiming);
    }

    split_all<<<14336, 256>>>(q, k, v, Wq, Wk, Wv, Wo);
    gemm3<<<dim3(8, 64, 3), 512, NSTG * STG>>>(pQ, pK, pV);
    attn_pass1<<<dim3(QT, BB * NH), 256>>>();

    // fork: pass2 (DRAM-bound, 0 smem) runs parallel to gemm_wo (tensor-bound)
    cudaEventRecord(ev_fork, 0);
    cudaStreamWaitEvent(s_tail, ev_fork, 0);
    if (do_attn)
        attn_pass2<<<dim3(KT, QT, BB * NH), 256, 0, s_tail>>>(attn);
    gemm_wo<<<dim3(8, 64), 512, NSTG * STG>>>(out);
    cudaEventRecord(ev_join, s_tail);
    cudaStreamWaitEvent(0, ev_join, 0);
}